// round 4
// baseline (speedup 1.0000x reference)
#include <cuda_runtime.h>
#include <cstdint>

// Problem constants: B=8, S=4096, H=16, E=64, s=64
#define NB 8
#define NH 16
#define NE 64
#define STOT 4096

#define TWO_PI 6.283185307179586476925f

__device__ float g_M[NH * 64 * 64];    // per-head dense operator M[h][n][j]
__device__ float g_zp[NH * 64];        // per-head zp[n]

__device__ __forceinline__ void cp16(float* dst, const float* src) {
    uint32_t s = (uint32_t)__cvta_generic_to_shared(dst);
    asm volatile("cp.async.cg.shared.global [%0], [%1], 16;" :: "r"(s), "l"(src));
}
__device__ __forceinline__ void cp_commit() {
    asm volatile("cp.async.commit_group;");
}

// ---------------------------------------------------------------------------
// Setup: 128 blocks = 16 heads x 8 n-chunks. Builds 8 rows of M_h per block
// directly from mod-indexed root tables (no big intermediate tables), plus
// the per-head zp[n] row sums.
//   M[n][j] = (1/126) sum_{k<64} c_k Re( Z[k] * conj(w127^{k(63+j)}) * w126^{kn} )
// ---------------------------------------------------------------------------
__global__ __launch_bounds__(256, 4)
void fftbias_setup(const float* __restrict__ w, const float* __restrict__ o_) {
    const int h = blockIdx.x >> 3;
    const int c = blockIdx.x & 7;          // n-chunk
    const int tid = threadIdx.x;

    __shared__ float2 root127[127];
    __shared__ float2 root126[126];
    __shared__ float2 Zsh[64];
    __shared__ float  zsh[127];
    __shared__ float  osh[64];
    __shared__ float  zp_s[8];

    if (tid < 127) {
        float sv, cv;
        sincosf(TWO_PI * (float)tid / 127.0f, &sv, &cv);
        root127[tid] = make_float2(cv, sv);
        zsh[tid] = w[h * 127 + tid];
    }
    if (tid < 126) {
        float sv, cv;
        sincosf(TWO_PI * (float)tid / 126.0f, &sv, &cv);
        root126[tid] = make_float2(cv, sv);
    }
    if (tid < 64) osh[tid] = o_[tid];
    if (tid < 8)  zp_s[tid] = 0.0f;
    __syncthreads();

    if (tid < 64) {                        // Z[k] = rfft_127(w_h)[k]
        const int k = tid;
        float zr = 0.f, zi = 0.f;
        int m = 0;
        for (int u = 0; u < 127; ++u) {
            float2 rt = root127[m];
            float zu = zsh[u];
            zr += zu * rt.x;
            zi -= zu * rt.y;
            m += k; if (m >= 127) m -= 127;
        }
        Zsh[k] = make_float2(zr, zi);
    }
    __syncthreads();

    #pragma unroll
    for (int r = 0; r < 2; ++r) {
        int idx = tid + r * 256;           // 0..511 : 8 n-rows x 64 j
        int nl = idx >> 6, j = idx & 63;
        int n = c * 8 + nl;
        int step1 = 63 + j;                // mod 127 index step
        int m1 = 0, m2 = 0;
        float acc = 0.f;
        for (int k = 0; k < 64; ++k) {
            float2 Zk = Zsh[k];
            float2 r1 = root127[m1];       // w127^{m1}; use conj
            float2 r2 = root126[m2];
            float ar = Zk.x * r1.x + Zk.y * r1.y;
            float ai = Zk.y * r1.x - Zk.x * r1.y;
            float re = ar * r2.x - ai * r2.y;
            float ck = (k == 0 || k == 63) ? 1.0f : 2.0f;
            acc += ck * re;
            m1 += step1; if (m1 >= 127) m1 -= 127;
            m2 += n;     while (m2 >= 126) m2 -= 126;
        }
        acc *= (1.0f / 126.0f);
        g_M[h * 4096 + n * 64 + j] = acc;
        atomicAdd(&zp_s[nl], 64.0f * acc * osh[j]);
    }
    __syncthreads();
    if (tid < 8) g_zp[h * 64 + c * 8 + tid] = zp_s[tid];
}

// ---------------------------------------------------------------------------
// z_pb writer: 64 blocks x 256 threads, coalesced [idx][h] stores.
// ---------------------------------------------------------------------------
__global__ __launch_bounds__(256, 4)
void fftbias_zpb(float* __restrict__ out2) {
    __shared__ float zp[NH * 64];
    const int tid = threadIdx.x;
    #pragma unroll
    for (int r = 0; r < 4; ++r) zp[tid + r * 256] = g_zp[tid + r * 256];
    __syncthreads();
    const int base = blockIdx.x * 64;      // 64 idx rows per block
    #pragma unroll
    for (int r = 0; r < 4; ++r) {
        int local = r * 256 + tid;         // 0..1023 = 64 idx x 16 h
        int idx = base + (local >> 4);
        int h = local & 15;
        int i = idx >> 6, j = idx & 63;
        out2[(size_t)idx * 16 + h] = zp[h * 64 + j] + zp[h * 64 + i];
    }
}

// ---------------------------------------------------------------------------
// Main: 512 blocks = (b,h) x 4 e-quarters, 256 threads, ~48KB smem
// (4 CTAs/SM).  Streams v slices through a 4-stage cp.async pipeline to get
// v_s/u_s, matvecs against L2-resident M_h (prefetched to smem), writes out.
// ---------------------------------------------------------------------------
__global__ __launch_bounds__(256, 4)
void fftbias_main(const float* __restrict__ v, float* __restrict__ out) {
    const int bx = blockIdx.x;
    const int b = bx >> 6;
    const int h = (bx >> 2) & 15;
    const int c = bx & 3;                  // e-quarter
    const int tid = threadIdx.x;
    const int e  = tid & 15;               // local e (0..15)
    const int gg = tid >> 4;               // 0..15

    extern __shared__ float sm[];
    float* slab = sm;                      // 4 stages * 1024
    float* Msh  = sm + 4096;               // 4096
    float* vs   = sm + 8192;               // 16*65
    float* us   = sm + 9232;               // 16*65
    float* rvs  = sm + 10272;              // 64*16  rv[n][e]
    float* rus  = sm + 11296;              // 64*16  ru[n][e]

    // base for this block's e-slice: element (t, eloc) at vb[t*1024 + eloc]
    const float* vb = v + ((size_t)b * STOT * NH + h) * NE + c * 16;

    // group 0: M_h into smem
    {
        const float* Msrc = g_M + h * 4096;
        #pragma unroll
        for (int r = 0; r < 4; ++r)
            cp16(Msh + (tid + r * 256) * 4, Msrc + (tid + r * 256) * 4);
        cp_commit();
    }
    // groups 1..3: first three slabs (1024 float4 slots each -> 1/thread... 256 slots)
    const int jj = tid >> 2;               // row within slab (0..63)
    const int q  = tid & 3;                // float4 slot (0..3)
    #pragma unroll
    for (int p = 0; p < 3; ++p) {
        cp16(slab + p * 1024 + jj * 16 + q * 4,
             vb + ((size_t)(p * 64 + jj)) * 1024 + q * 4);
        cp_commit();
    }

    for (int idx = tid; idx < 16 * 65; idx += 256) us[idx] = 0.f;
    __syncthreads();

    // ---- Phase 1: pipelined streaming reduce -------------------------------
    float vacc[4];
    #pragma unroll
    for (int k = 0; k < 4; ++k) vacc[k] = 0.f;

    for (int i = 0; i < 64; ++i) {
        asm volatile("cp.async.wait_group 2;");
        __syncthreads();

        if (i + 3 < 64) {
            int ip = i + 3, st = ip & 3;
            cp16(slab + st * 1024 + jj * 16 + q * 4,
                 vb + ((size_t)(ip * 64 + jj)) * 1024 + q * 4);
        }
        cp_commit();

        const float* sl = slab + (i & 3) * 1024;
        float up = 0.f;
        #pragma unroll
        for (int k = 0; k < 4; ++k) {
            float x = sl[(gg + 16 * k) * 16 + e];
            vacc[k] += x;                  // v_s[e][gg+16k] partial over i
            up += x;                       // u_s[e][i] partial over j-subset
        }
        atomicAdd(&us[e * 65 + i], up);
    }

    #pragma unroll
    for (int k = 0; k < 4; ++k) vs[e * 65 + gg + 16 * k] = vacc[k];
    __syncthreads();

    // ---- Phase 2: dense 64x64 matvec per local e ---------------------------
    float rv[4], ru[4];
    #pragma unroll
    for (int k = 0; k < 4; ++k) { rv[k] = 0.f; ru[k] = 0.f; }

    for (int j = 0; j < 64; ++j) {
        float a  = vs[e * 65 + j];
        float bb = us[e * 65 + j];
        #pragma unroll
        for (int k = 0; k < 4; ++k) {
            float m = Msh[(gg + 16 * k) * 64 + j];
            rv[k] += m * a;
            ru[k] += m * bb;
        }
    }
    #pragma unroll
    for (int k = 0; k < 4; ++k) {
        int n = gg + 16 * k;
        rvs[n * 16 + e] = rv[k];
        rus[n * 16 + e] = ru[k];
    }
    __syncthreads();

    // ---- Phase 3: streaming stores -----------------------------------------
    // thread (q, rr): per r writes row t = r*64 + rr  (i = r, j = rr)
    const int rr = tid >> 2;               // 0..63
    float* ob = out + ((size_t)b * STOT * NH + h) * NE + c * 16;
    float4 a = *(const float4*)&rvs[rr * 16 + q * 4];   // loop-invariant
    #pragma unroll 4
    for (int r = 0; r < 64; ++r) {
        float4 cc = *(const float4*)&rus[r * 16 + q * 4];
        float4 o4 = make_float4(a.x + cc.x, a.y + cc.y, a.z + cc.z, a.w + cc.w);
        __stcs((float4*)&ob[((size_t)(r * 64 + rr)) * 1024 + q * 4], o4);
    }
}

// ---------------------------------------------------------------------------
extern "C" void kernel_launch(void* const* d_in, const int* in_sizes, int n_in,
                              void* d_out, int out_size) {
    const float* v  = (const float*)d_in[0];   // (8,4096,16,64) f32
    const float* w  = (const float*)d_in[1];   // (1,16,127) f32
    const float* o_ = (const float*)d_in[2];   // (64,) f32
    float* out  = (float*)d_out;
    float* out2 = out + (size_t)NB * STOT * NH * NE;   // z_pb region

    const int smem_main = 12320 * 4;   // 49280 B

    cudaFuncSetAttribute(fftbias_main,
                         cudaFuncAttributeMaxDynamicSharedMemorySize, smem_main);

    fftbias_setup<<<128, 256>>>(w, o_);
    fftbias_zpb<<<64, 256>>>(out2);
    fftbias_main<<<NB * NH * 4, 256, smem_main>>>(v, out);
}